// round 2
// baseline (speedup 1.0000x reference)
#include <cuda_runtime.h>
#include <math.h>

#define BATCH 8
#define C 96
#define HW 128
#define IMG (HW*HW)          // 16384
#define PLANE (C*IMG)        // 1572864
#define TOT (BATCH*PLANE)    // 12582912
#define KK 9
#define CKK (C*KK)           // 864
#define ASPLIT 6             // split of the 42 patch-rows into 6 chunks of 7
#define LN_EPS 1e-5

// ---------------- scratch (device globals; no allocation allowed) -------------
__device__ float g_x1[TOT];     // x1_out = sc1*x1 + x1n
__device__ float g_x2[TOT];     // x2_out
__device__ float g_xr[TOT];     // residual branch output
__device__ float g_key[TOT];    // conv(x1_out, aw1)
__device__ float g_qry[TOT];    // conv(x2_out, aw2)
__device__ float g_val[TOT];    // conv(x1_out, aw3)
__device__ float g_c2[TOT];     // conv(x2_out, w_conv2)
__device__ float g_att[TOT];    // per-example attention conv output
__device__ float g_attp[ASPLIT*BATCH*C*CKK];  // partial logits
__device__ float g_attw[BATCH*C*CKK];         // softmax weights [b][q][c][3][3]
__device__ double g_stats[96];
__device__ float g_coef[BATCH*16];

// stats layout:
//  [b]               : sum(x)                      (pass 1)
//  [8 + 5b + 0..4]   : pos, s1, s1sq, s2, s2sq    (pass 2, on centered x)
//  [48 + 2b, +1]     : sum, sumsq of g_att        (pass 3)
//  [64 + 2b, +1]     : sum, sumsq of g_c2         (pass 3)
// coef layout (per b, 16 floats):
//  0:m0 1:A1 2:B1 3:D1 4:A2 5:B2 6:D2 7:sc1 8:mA 9:invA 10:mC 11:invC
//  12:sc2 13:res_coef 14:nc1 15:nc2

__device__ __forceinline__ float* dev_buf(int s) {
    switch (s) {
        case 0: return g_x1;  case 1: return g_x2;  case 2: return g_xr;
        case 3: return g_key; case 4: return g_qry; case 5: return g_val;
        case 6: return g_c2;  case 7: return g_att; case 8: return g_attw;
    }
    return 0;
}

// ---------------- small helpers ----------------------------------------------
__device__ __forceinline__ double blk_reduce_d(double v, double* red) {
    int tid = threadIdx.x;
    red[tid] = v; __syncthreads();
    for (int s = blockDim.x >> 1; s > 0; s >>= 1) {
        if (tid < s) red[tid] += red[tid + s];
        __syncthreads();
    }
    double r = red[0]; __syncthreads();
    return r;
}

// ---------------- stage 0: stats ---------------------------------------------
__global__ void zero_stats_kernel() {
    if (threadIdx.x < 96) g_stats[threadIdx.x] = 0.0;
}

__global__ void reduce_sum_kernel(const float* __restrict__ x) {
    __shared__ double red[256];
    int b = blockIdx.y;
    const float* xp = x + (size_t)b * PLANE;
    double s = 0.0;
    for (int i = blockIdx.x * 256 + threadIdx.x; i < PLANE; i += 32 * 256)
        s += (double)xp[i];
    s = blk_reduce_d(s, red);
    if (threadIdx.x == 0) atomicAdd(&g_stats[b], s);
}

__global__ void reduce_pass2_kernel(const float* __restrict__ x) {
    __shared__ double red[256];
    int b = blockIdx.y;
    float m0 = (float)(g_stats[b] * (1.0 / (double)PLANE));
    const float* xp = x + (size_t)b * PLANE;
    double pos = 0, s1 = 0, s1sq = 0, s2 = 0, s2sq = 0;
    for (int i = blockIdx.x * 256 + threadIdx.x; i < PLANE; i += 32 * 256) {
        float xc = xp[i] - m0;
        double d = (double)xc;
        if (xc > 0.f) { pos += 1.0; s1 += d; s1sq += d * d; }
        else          { s2 += d; s2sq += d * d; }
    }
    double r;
    r = blk_reduce_d(pos, red);  if (threadIdx.x == 0) atomicAdd(&g_stats[8 + 5*b + 0], r);
    r = blk_reduce_d(s1,  red);  if (threadIdx.x == 0) atomicAdd(&g_stats[8 + 5*b + 1], r);
    r = blk_reduce_d(s1sq,red);  if (threadIdx.x == 0) atomicAdd(&g_stats[8 + 5*b + 2], r);
    r = blk_reduce_d(s2,  red);  if (threadIdx.x == 0) atomicAdd(&g_stats[8 + 5*b + 3], r);
    r = blk_reduce_d(s2sq,red);  if (threadIdx.x == 0) atomicAdd(&g_stats[8 + 5*b + 4], r);
}

__global__ void finalize1_kernel(const float* __restrict__ sc1p,
                                 const float* __restrict__ sc2p,
                                 const float* __restrict__ resp,
                                 const float* __restrict__ nc1p,
                                 const float* __restrict__ nc2p) {
    int b = threadIdx.x;
    if (b >= BATCH) return;
    const double N = (double)PLANE;
    double m0   = g_stats[b] / N;
    double pos  = g_stats[8 + 5*b + 0];
    double s1   = g_stats[8 + 5*b + 1];
    double s1sq = g_stats[8 + 5*b + 2];
    double s2   = g_stats[8 + 5*b + 3];
    double s2sq = g_stats[8 + 5*b + 4];
    double neg  = N - pos;
    double avg1 = s1 / pos;
    double avg2 = s2 / neg;
    double mu1  = (s1 + avg1 * neg) / N;
    double var1 = (s1sq + avg1 * avg1 * neg) / N - mu1 * mu1;
    double inv1 = 1.0 / sqrt(var1 + LN_EPS);
    double c1   = sqrt(pos / N);
    double A1   = c1 * inv1;
    double mu2  = (s2 + avg2 * pos) / N;
    double var2 = (s2sq + avg2 * avg2 * pos) / N - mu2 * mu2;
    double inv2 = 1.0 / sqrt(var2 + LN_EPS);
    double c2   = sqrt(neg / N);
    double A2   = c2 * inv2;
    float* cf = &g_coef[b * 16];
    cf[0] = (float)m0;
    cf[1] = (float)A1;
    cf[2] = (float)(-A1 * mu1);
    cf[3] = (float)(A1 * (avg1 - mu1));
    cf[4] = (float)A2;
    cf[5] = (float)(-A2 * mu2);
    cf[6] = (float)(A2 * (avg2 - mu2));
    cf[7]  = *sc1p;
    cf[12] = *sc2p;
    cf[13] = *resp;
    cf[14] = *nc1p;
    cf[15] = *nc2p;
}

// ---------------- stage 1: split-norm elementwise ----------------------------
__global__ void elementwise_kernel(const float* __restrict__ x) {
    int b = blockIdx.y;
    const float* cf = &g_coef[b * 16];
    float m0 = cf[0], A1 = cf[1], B1 = cf[2], D1 = cf[3];
    float A2 = cf[4], B2 = cf[5], D2 = cf[6];
    float sc1 = cf[7], sc2 = cf[12], res = cf[13], nc1 = cf[14], nc2 = cf[15];
    size_t base = (size_t)b * PLANE + (size_t)(blockIdx.x * 256 + threadIdx.x) * 4;
    float4 xv = *(const float4*)(x + base);
    float4 r1, r2, rr;
    float in[4] = {xv.x, xv.y, xv.z, xv.w};
    float o1[4], o2[4], orr[4];
#pragma unroll
    for (int k = 0; k < 4; k++) {
        float xc = in[k] - m0;
        float x1v, x1n, x2v, x2n;
        if (xc > 0.f) { x1v = xc; x1n = fmaf(A1, xc, B1); x2v = 0.f; x2n = D2; }
        else          { x1v = 0.f; x1n = D1; x2v = xc; x2n = fmaf(A2, xc, B2); }
        orr[k] = 0.5f * (nc1 * x1n + nc2 * x2n) + res * xc;
        o1[k]  = sc1 * x1v + x1n;
        o2[k]  = sc2 * x2v + x2n;
    }
    r1.x = o1[0]; r1.y = o1[1]; r1.z = o1[2]; r1.w = o1[3];
    r2.x = o2[0]; r2.y = o2[1]; r2.z = o2[2]; r2.w = o2[3];
    rr.x = orr[0]; rr.y = orr[1]; rr.z = orr[2]; rr.w = orr[3];
    *(float4*)(g_x1 + base) = r1;
    *(float4*)(g_x2 + base) = r2;
    *(float4*)(g_xr + base) = rr;
}

// ---------------- stage 2: 3x3 convolutions ----------------------------------
// tile 32x16, 2x2 micro-tile per thread (16x8 threads = 128), 16 out-ch/block
#define TW 32
#define TH 16
#define COB 16
__global__ void __launch_bounds__(128)
conv3x3_kernel(int in_sel, const float* __restrict__ w_ext, int w_sel,
               int out_sel, int per_batch) {
    const float* in  = dev_buf(in_sel);
    const float* w   = (w_sel >= 0) ? dev_buf(w_sel) : w_ext;
    float* out       = dev_buf(out_sel);

    int bz  = blockIdx.z;
    int b   = bz / (C / COB);
    int cog = bz % (C / COB);
    int x0  = blockIdx.x * TW;
    int y0  = blockIdx.y * TH;
    int tx  = threadIdx.x;            // 0..15
    int ty  = threadIdx.y;            // 0..7
    int tid = ty * 16 + tx;

    __shared__ float tile[18][36];
    __shared__ float wsm[COB][9];

    const float* wbase = w + (per_batch ? (size_t)b * C * C * 9 : 0)
                           + (size_t)(cog * COB) * C * 9;
    const float* inb = in + (size_t)b * PLANE;

    float acc[COB][4];
#pragma unroll
    for (int i = 0; i < COB; i++) {
        acc[i][0] = 0.f; acc[i][1] = 0.f; acc[i][2] = 0.f; acc[i][3] = 0.f;
    }

    for (int ci = 0; ci < C; ci++) {
        __syncthreads();
        const float* ip = inb + (size_t)ci * IMG;
        for (int idx = tid; idx < 18 * 34; idx += 128) {
            int r = idx / 34, cc = idx % 34;
            int gy = y0 - 1 + r, gx = x0 - 1 + cc;
            float v = 0.f;
            if (gy >= 0 && gy < HW && gx >= 0 && gx < HW) v = ip[gy * HW + gx];
            tile[r][cc] = v;
        }
        for (int idx = tid; idx < COB * 9; idx += 128)
            wsm[idx / 9][idx % 9] = wbase[(idx / 9) * C * 9 + ci * 9 + (idx % 9)];
        __syncthreads();

        float win[4][4];
#pragma unroll
        for (int r = 0; r < 4; r++)
#pragma unroll
            for (int cc = 0; cc < 4; cc++)
                win[r][cc] = tile[2 * ty + r][2 * tx + cc];

#pragma unroll
        for (int co = 0; co < COB; co++) {
            float w0 = wsm[co][0], w1 = wsm[co][1], w2 = wsm[co][2];
            float w3 = wsm[co][3], w4 = wsm[co][4], w5 = wsm[co][5];
            float w6 = wsm[co][6], w7 = wsm[co][7], w8 = wsm[co][8];
#pragma unroll
            for (int dy = 0; dy < 2; dy++)
#pragma unroll
                for (int dx = 0; dx < 2; dx++) {
                    float s;
                    s  = win[dy + 0][dx + 0] * w0;
                    s  = fmaf(win[dy + 0][dx + 1], w1, s);
                    s  = fmaf(win[dy + 0][dx + 2], w2, s);
                    s  = fmaf(win[dy + 1][dx + 0], w3, s);
                    s  = fmaf(win[dy + 1][dx + 1], w4, s);
                    s  = fmaf(win[dy + 1][dx + 2], w5, s);
                    s  = fmaf(win[dy + 2][dx + 0], w6, s);
                    s  = fmaf(win[dy + 2][dx + 1], w7, s);
                    s  = fmaf(win[dy + 2][dx + 2], w8, s);
                    acc[co][dy * 2 + dx] += s;
                }
        }
    }

#pragma unroll
    for (int co = 0; co < COB; co++) {
        size_t ob = ((size_t)b * C + cog * COB + co) * IMG;
#pragma unroll
        for (int dy = 0; dy < 2; dy++)
#pragma unroll
            for (int dx = 0; dx < 2; dx++)
                out[ob + (size_t)(y0 + 2 * ty + dy) * HW + (x0 + 2 * tx + dx)]
                    = acc[co][dy * 2 + dx];
    }
}

// ---------------- stage 3: attention logits ----------------------------------
// attn[b,q,c,t] = sum over pixels (3ho+kh, 3wo+kw), ho,wo in [0,42)
__global__ void __launch_bounds__(256)
attn_logits_kernel() {
    int gz = blockIdx.x;
    int s = gz % ASPLIT; gz /= ASPLIT;
    int t = gz % 9;
    int b = gz / 9;
    int kh = t / 3, kw = t % 3;
    int tid = threadIdx.x;
    int qx = tid & 15;   // q tile index
    int cy = tid >> 4;   // c tile index

    __shared__ float Qs[42][97];
    __shared__ float Ks[42][97];

    float acc[6][6];
#pragma unroll
    for (int i = 0; i < 6; i++)
#pragma unroll
        for (int j = 0; j < 6; j++) acc[i][j] = 0.f;

    for (int ho = s * 7; ho < s * 7 + 7; ho++) {
        __syncthreads();
        int row = 3 * ho + kh;
        for (int idx = tid; idx < C * 42; idx += 256) {
            int ch = idx / 42, p = idx % 42;
            size_t a = ((size_t)b * C + ch) * IMG + (size_t)row * HW + (3 * p + kw);
            Qs[p][ch] = g_qry[a];
            Ks[p][ch] = g_key[a];
        }
        __syncthreads();
#pragma unroll 2
        for (int p = 0; p < 42; p++) {
            float qv[6], kv[6];
#pragma unroll
            for (int i = 0; i < 6; i++) {
                qv[i] = Qs[p][qx * 6 + i];
                kv[i] = Ks[p][cy * 6 + i];
            }
#pragma unroll
            for (int i = 0; i < 6; i++)
#pragma unroll
                for (int j = 0; j < 6; j++)
                    acc[i][j] = fmaf(kv[i], qv[j], acc[i][j]);
        }
    }
#pragma unroll
    for (int i = 0; i < 6; i++)
#pragma unroll
        for (int j = 0; j < 6; j++) {
            int q = qx * 6 + j, c = cy * 6 + i;
            g_attp[(((size_t)s * BATCH + b) * C + q) * CKK + c * 9 + t] = acc[i][j];
        }
}

// ---------------- stage 4: softmax over (c,t) --------------------------------
__global__ void __launch_bounds__(128)
softmax_kernel() {
    int b = blockIdx.x / C, q = blockIdx.x % C;
    int tid = threadIdx.x;
    __shared__ float red[128];
    const float scale = 0.034020690871988617f;   // 1/sqrt(864)

    float vals[7];
    float mx = -1e30f;
#pragma unroll
    for (int k = 0; k < 7; k++) {
        int j = tid + k * 128;
        if (j < CKK) {
            float v = 0.f;
#pragma unroll
            for (int s = 0; s < ASPLIT; s++)
                v += g_attp[(((size_t)s * BATCH + b) * C + q) * CKK + j];
            v *= scale;
            vals[k] = v;
            mx = fmaxf(mx, v);
        } else vals[k] = -1e30f;
    }
    red[tid] = mx; __syncthreads();
    for (int s = 64; s > 0; s >>= 1) {
        if (tid < s) red[tid] = fmaxf(red[tid], red[tid + s]);
        __syncthreads();
    }
    float M = red[0]; __syncthreads();

    float sum = 0.f;
#pragma unroll
    for (int k = 0; k < 7; k++) {
        int j = tid + k * 128;
        if (j < CKK) { vals[k] = expf(vals[k] - M); sum += vals[k]; }
    }
    red[tid] = sum; __syncthreads();
    for (int s = 64; s > 0; s >>= 1) {
        if (tid < s) red[tid] += red[tid + s];
        __syncthreads();
    }
    float inv = 1.f / red[0];
#pragma unroll
    for (int k = 0; k < 7; k++) {
        int j = tid + k * 128;
        if (j < CKK) g_attw[((size_t)b * C + q) * CKK + j] = vals[k] * inv;
    }
}

// ---------------- stage 5: mean/var of g_att and g_c2 ------------------------
__global__ void reduce_mv_kernel() {
    __shared__ double red[256];
    int b = blockIdx.y;
    int z = blockIdx.z;
    const float* p = (z == 0 ? g_att : g_c2) + (size_t)b * PLANE;
    double s = 0, sq = 0;
    for (int i = blockIdx.x * 256 + threadIdx.x; i < PLANE; i += 32 * 256) {
        double v = (double)p[i];
        s += v; sq += v * v;
    }
    double r;
    r = blk_reduce_d(s,  red); if (threadIdx.x == 0) atomicAdd(&g_stats[48 + z * 16 + 2 * b], r);
    r = blk_reduce_d(sq, red); if (threadIdx.x == 0) atomicAdd(&g_stats[48 + z * 16 + 2 * b + 1], r);
}

__global__ void finalize2_kernel() {
    int b = threadIdx.x;
    if (b >= BATCH) return;
    const double N = (double)PLANE;
    double mA = g_stats[48 + 2 * b] / N;
    double vA = g_stats[48 + 2 * b + 1] / N - mA * mA;
    double mC = g_stats[64 + 2 * b] / N;
    double vC = g_stats[64 + 2 * b + 1] / N - mC * mC;
    float* cf = &g_coef[b * 16];
    cf[8]  = (float)mA;
    cf[9]  = (float)(1.0 / sqrt(vA + LN_EPS));
    cf[10] = (float)mC;
    cf[11] = (float)(1.0 / sqrt(vC + LN_EPS));
}

// ---------------- stage 6: fused layer_norms + gate + 1x1 conv + residual ----
// block: 32 pixels, all 96 outputs (4 chunks of 24), 192 threads.
// smem: wfT chunk [192 c][24 o] stride 28 (21.5KB) + ys [192 c][32 px] (24.6KB)
// => 46.1KB static shared, no cudaFuncSetAttribute needed.
#define FPX 32
#define FTHREADS 192
#define WPAD 28

__global__ void __launch_bounds__(FTHREADS)
final_kernel(const float* __restrict__ wf, const float* __restrict__ bias,
             float* __restrict__ outp) {
    __shared__ float wfT[192 * WPAD];   // [c][o_local], padded
    __shared__ float ys[192 * FPX];     // [c][px]

    int b  = blockIdx.y;
    int p0 = blockIdx.x * FPX;
    int tid = threadIdx.x;
    int oo = tid >> 5;        // 0..5  -> 4 outputs each within chunk
    int pp = tid & 31;        // 0..31 -> pixel

    const float* cf = &g_coef[b * 16];
    float mA = cf[8], invA = cf[9], mC = cf[10], invC = cf[11];

    // load y tile once: c in [0,192), 32 px
    for (int idx = tid; idx < 192 * FPX; idx += FTHREADS) {
        int c = idx >> 5, p = idx & 31;
        float v;
        if (c < 96) {
            v = (g_att[((size_t)b * C + c) * IMG + p0 + p] - mA) * invA;
        } else {
            int cc = c - 96;
            size_t a = ((size_t)b * C + cc) * IMG + p0 + p;
            v = (g_c2[a] - mC) * invC * g_x1[a];
        }
        ys[c * FPX + p] = v;
    }

    for (int og = 0; og < 4; og++) {
        __syncthreads();
        // load weight chunk: outputs [og*24, og*24+24), all 192 c
        for (int idx = tid; idx < 24 * 192; idx += FTHREADS) {
            int o = idx / 192, c = idx % 192;
            wfT[c * WPAD + o] = wf[(og * 24 + o) * 192 + c];
        }
        __syncthreads();

        float acc0 = 0.f, acc1 = 0.f, acc2 = 0.f, acc3 = 0.f;
#pragma unroll 4
        for (int c = 0; c < 192; c++) {
            float4 w4 = *(const float4*)(wfT + c * WPAD + oo * 4);
            float yv = ys[c * FPX + pp];
            acc0 = fmaf(w4.x, yv, acc0);
            acc1 = fmaf(w4.y, yv, acc1);
            acc2 = fmaf(w4.z, yv, acc2);
            acc3 = fmaf(w4.w, yv, acc3);
        }

        int obase = og * 24 + oo * 4;
        float accv[4] = {acc0, acc1, acc2, acc3};
#pragma unroll
        for (int i = 0; i < 4; i++) {
            int o = obase + i;
            size_t ob = ((size_t)b * C + o) * IMG + p0 + pp;
            outp[ob] = g_xr[ob] + __ldg(&bias[o]) + accv[i];
        }
    }
}

// ---------------- launcher ----------------------------------------------------
extern "C" void kernel_launch(void* const* d_in, const int* in_sizes, int n_in,
                              void* d_out, int out_size) {
    const float* x      = (const float*)d_in[0];
    const float* wconv2 = (const float*)d_in[1];
    const float* aw1    = (const float*)d_in[2];
    const float* aw2    = (const float*)d_in[3];
    const float* aw3    = (const float*)d_in[4];
    const float* wfull  = (const float*)d_in[5];
    const float* bfull  = (const float*)d_in[6];
    const float* sc1    = (const float*)d_in[7];
    const float* sc2    = (const float*)d_in[8];
    const float* resc   = (const float*)d_in[9];
    const float* nc1    = (const float*)d_in[10];
    const float* nc2    = (const float*)d_in[11];
    float* outp = (float*)d_out;

    zero_stats_kernel<<<1, 128>>>();
    reduce_sum_kernel<<<dim3(32, BATCH), 256>>>(x);
    reduce_pass2_kernel<<<dim3(32, BATCH), 256>>>(x);
    finalize1_kernel<<<1, 32>>>(sc1, sc2, resc, nc1, nc2);
    elementwise_kernel<<<dim3(PLANE / 1024, BATCH), 256>>>(x);

    dim3 cgrid(HW / TW, HW / TH, BATCH * (C / COB));
    dim3 cblk(16, 8);
    conv3x3_kernel<<<cgrid, cblk>>>(0, aw1,    -1, 3, 0);  // key = conv(x1, aw1)
    conv3x3_kernel<<<cgrid, cblk>>>(1, aw2,    -1, 4, 0);  // qry = conv(x2, aw2)
    conv3x3_kernel<<<cgrid, cblk>>>(0, aw3,    -1, 5, 0);  // val = conv(x1, aw3)
    conv3x3_kernel<<<cgrid, cblk>>>(1, wconv2, -1, 6, 0);  // c2  = conv(x2, w_conv2)

    attn_logits_kernel<<<BATCH * 9 * ASPLIT, 256>>>();
    softmax_kernel<<<BATCH * C, 128>>>();

    conv3x3_kernel<<<cgrid, cblk>>>(5, (const float*)0, 8, 7, 1);  // per-example conv

    reduce_mv_kernel<<<dim3(32, BATCH, 2), 256>>>();
    finalize2_kernel<<<1, 32>>>();

    final_kernel<<<dim3(IMG / FPX, BATCH), FTHREADS>>>(wfull, bfull, outp);
}

// round 3
// speedup vs baseline: 1.2316x; 1.2316x over previous
#include <cuda_runtime.h>
#include <math.h>

#define BATCH 8
#define C 96
#define HW 128
#define IMG (HW*HW)          // 16384
#define PLANE (C*IMG)        // 1572864
#define TOT (BATCH*PLANE)    // 12582912
#define KK 9
#define CKK (C*KK)           // 864
#define ASPLIT 6             // split of the 42 patch-rows into 6 chunks of 7
#define LN_EPS 1e-5

typedef unsigned long long ull;

// ---------------- f32x2 packed math helpers ----------------------------------
__device__ __forceinline__ ull pk2(float a, float b) {
    ull r;
    asm("mov.b64 %0, {%1, %2};" : "=l"(r) : "f"(a), "f"(b));
    return r;
}
__device__ __forceinline__ void upk2(ull v, float& a, float& b) {
    asm("mov.b64 {%0, %1}, %2;" : "=f"(a), "=f"(b) : "l"(v));
}
__device__ __forceinline__ ull fma2(ull a, ull b, ull c) {
    ull d;
    asm("fma.rn.f32x2 %0, %1, %2, %3;" : "=l"(d) : "l"(a), "l"(b), "l"(c));
    return d;
}

// ---------------- scratch (device globals; no allocation allowed) -------------
__device__ float g_x1[TOT];     // x1_out = sc1*x1 + x1n
__device__ float g_x2[TOT];     // x2_out
__device__ float g_xr[TOT];     // residual branch output
__device__ float g_key[TOT];    // conv(x1_out, aw1)
__device__ float g_qry[TOT];    // conv(x2_out, aw2)
__device__ float g_val[TOT];    // conv(x1_out, aw3)
__device__ float g_c2[TOT];     // conv(x2_out, w_conv2)
__device__ float g_att[TOT];    // per-example attention conv output
__device__ float g_attp[ASPLIT*BATCH*C*CKK];  // partial logits
__device__ float g_attw[BATCH*C*CKK];         // softmax weights [b][q][c][3][3]
__device__ double g_stats[96];
__device__ float g_coef[BATCH*16];

// stats layout:
//  [b]               : sum(x)                      (pass 1)
//  [8 + 5b + 0..4]   : pos, s1, s1sq, s2, s2sq    (pass 2, on centered x)
//  [48 + 2b, +1]     : sum, sumsq of g_att        (fused into attn conv)
//  [64 + 2b, +1]     : sum, sumsq of g_c2         (fused into c2 conv)
// coef layout (per b, 16 floats):
//  0:m0 1:A1 2:B1 3:D1 4:A2 5:B2 6:D2 7:sc1 8:mA 9:invA 10:mC 11:invC
//  12:sc2 13:res_coef 14:nc1 15:nc2

__device__ __forceinline__ float* dev_buf(int s) {
    switch (s) {
        case 0: return g_x1;  case 1: return g_x2;  case 2: return g_xr;
        case 3: return g_key; case 4: return g_qry; case 5: return g_val;
        case 6: return g_c2;  case 7: return g_att; case 8: return g_attw;
    }
    return 0;
}

// ---------------- small helpers ----------------------------------------------
__device__ __forceinline__ double blk_reduce_d(double v, double* red, int nthr) {
    int tid = threadIdx.x;
    red[tid] = v; __syncthreads();
    for (int s = nthr >> 1; s > 0; s >>= 1) {
        if (tid < s) red[tid] += red[tid + s];
        __syncthreads();
    }
    double r = red[0]; __syncthreads();
    return r;
}

// ---------------- stage 0: stats ---------------------------------------------
__global__ void zero_stats_kernel() {
    if (threadIdx.x < 96) g_stats[threadIdx.x] = 0.0;
}

__global__ void reduce_sum_kernel(const float* __restrict__ x) {
    __shared__ double red[256];
    int b = blockIdx.y;
    const float* xp = x + (size_t)b * PLANE;
    double s = 0.0;
    for (int i = blockIdx.x * 256 + threadIdx.x; i < PLANE; i += 32 * 256)
        s += (double)xp[i];
    s = blk_reduce_d(s, red, 256);
    if (threadIdx.x == 0) atomicAdd(&g_stats[b], s);
}

__global__ void reduce_pass2_kernel(const float* __restrict__ x) {
    __shared__ double red[256];
    int b = blockIdx.y;
    float m0 = (float)(g_stats[b] * (1.0 / (double)PLANE));
    const float* xp = x + (size_t)b * PLANE;
    double pos = 0, s1 = 0, s1sq = 0, s2 = 0, s2sq = 0;
    for (int i = blockIdx.x * 256 + threadIdx.x; i < PLANE; i += 32 * 256) {
        float xc = xp[i] - m0;
        double d = (double)xc;
        if (xc > 0.f) { pos += 1.0; s1 += d; s1sq += d * d; }
        else          { s2 += d; s2sq += d * d; }
    }
    double r;
    r = blk_reduce_d(pos, red, 256);  if (threadIdx.x == 0) atomicAdd(&g_stats[8 + 5*b + 0], r);
    r = blk_reduce_d(s1,  red, 256);  if (threadIdx.x == 0) atomicAdd(&g_stats[8 + 5*b + 1], r);
    r = blk_reduce_d(s1sq,red, 256);  if (threadIdx.x == 0) atomicAdd(&g_stats[8 + 5*b + 2], r);
    r = blk_reduce_d(s2,  red, 256);  if (threadIdx.x == 0) atomicAdd(&g_stats[8 + 5*b + 3], r);
    r = blk_reduce_d(s2sq,red, 256);  if (threadIdx.x == 0) atomicAdd(&g_stats[8 + 5*b + 4], r);
}

__global__ void finalize1_kernel(const float* __restrict__ sc1p,
                                 const float* __restrict__ sc2p,
                                 const float* __restrict__ resp,
                                 const float* __restrict__ nc1p,
                                 const float* __restrict__ nc2p) {
    int b = threadIdx.x;
    if (b >= BATCH) return;
    const double N = (double)PLANE;
    double m0   = g_stats[b] / N;
    double pos  = g_stats[8 + 5*b + 0];
    double s1   = g_stats[8 + 5*b + 1];
    double s1sq = g_stats[8 + 5*b + 2];
    double s2   = g_stats[8 + 5*b + 3];
    double s2sq = g_stats[8 + 5*b + 4];
    double neg  = N - pos;
    double avg1 = s1 / pos;
    double avg2 = s2 / neg;
    double mu1  = (s1 + avg1 * neg) / N;
    double var1 = (s1sq + avg1 * avg1 * neg) / N - mu1 * mu1;
    double inv1 = 1.0 / sqrt(var1 + LN_EPS);
    double c1   = sqrt(pos / N);
    double A1   = c1 * inv1;
    double mu2  = (s2 + avg2 * pos) / N;
    double var2 = (s2sq + avg2 * avg2 * pos) / N - mu2 * mu2;
    double inv2 = 1.0 / sqrt(var2 + LN_EPS);
    double c2   = sqrt(neg / N);
    double A2   = c2 * inv2;
    float* cf = &g_coef[b * 16];
    cf[0] = (float)m0;
    cf[1] = (float)A1;
    cf[2] = (float)(-A1 * mu1);
    cf[3] = (float)(A1 * (avg1 - mu1));
    cf[4] = (float)A2;
    cf[5] = (float)(-A2 * mu2);
    cf[6] = (float)(A2 * (avg2 - mu2));
    cf[7]  = *sc1p;
    cf[12] = *sc2p;
    cf[13] = *resp;
    cf[14] = *nc1p;
    cf[15] = *nc2p;
}

// ---------------- stage 1: split-norm elementwise ----------------------------
__global__ void elementwise_kernel(const float* __restrict__ x) {
    int b = blockIdx.y;
    const float* cf = &g_coef[b * 16];
    float m0 = cf[0], A1 = cf[1], B1 = cf[2], D1 = cf[3];
    float A2 = cf[4], B2 = cf[5], D2 = cf[6];
    float sc1 = cf[7], sc2 = cf[12], res = cf[13], nc1 = cf[14], nc2 = cf[15];
    size_t base = (size_t)b * PLANE + (size_t)(blockIdx.x * 256 + threadIdx.x) * 4;
    float4 xv = *(const float4*)(x + base);
    float4 r1, r2, rr;
    float in[4] = {xv.x, xv.y, xv.z, xv.w};
    float o1[4], o2[4], orr[4];
#pragma unroll
    for (int k = 0; k < 4; k++) {
        float xc = in[k] - m0;
        float x1v, x1n, x2v, x2n;
        if (xc > 0.f) { x1v = xc; x1n = fmaf(A1, xc, B1); x2v = 0.f; x2n = D2; }
        else          { x1v = 0.f; x1n = D1; x2v = xc; x2n = fmaf(A2, xc, B2); }
        orr[k] = 0.5f * (nc1 * x1n + nc2 * x2n) + res * xc;
        o1[k]  = sc1 * x1v + x1n;
        o2[k]  = sc2 * x2v + x2n;
    }
    r1.x = o1[0]; r1.y = o1[1]; r1.z = o1[2]; r1.w = o1[3];
    r2.x = o2[0]; r2.y = o2[1]; r2.z = o2[2]; r2.w = o2[3];
    rr.x = orr[0]; rr.y = orr[1]; rr.z = orr[2]; rr.w = orr[3];
    *(float4*)(g_x1 + base) = r1;
    *(float4*)(g_x2 + base) = r2;
    *(float4*)(g_xr + base) = rr;
}

// ---------------- stage 2: 3x3 convolutions (packed f32x2) --------------------
// tile 32x32 px per block, 128 threads (16x in x, 8 in y).
// Each thread: 8 output px = 2(x) * 2(y-base: ty, ty+8) * pair(y, y+16),
// packed into 4 ull accumulators per output channel; COB=8 channels/block.
#define TW 32
#define TH 32
#define COB 8
#define TSTRIDE 37

__global__ void __launch_bounds__(128)
conv3x3_kernel(int in_sel, const float* __restrict__ w_ext, int w_sel,
               int out_sel, int per_batch, int stats_base) {
    const float* in  = dev_buf(in_sel);
    const float* w   = (w_sel >= 0) ? dev_buf(w_sel) : w_ext;
    float* out       = dev_buf(out_sel);

    int bz  = blockIdx.z;
    int b   = bz / (C / COB);
    int cog = bz % (C / COB);
    int x0  = blockIdx.x * TW;
    int y0  = blockIdx.y * TH;
    int tid = threadIdx.x;
    int tx  = tid & 15;           // 0..15
    int ty  = tid >> 4;           // 0..7

    __shared__ float tile[34 * TSTRIDE];
    __shared__ ull   wsm2[COB * 9];
    __shared__ double sred[128];

    const float* wbase = w + (per_batch ? (size_t)b * C * C * 9 : 0)
                           + (size_t)(cog * COB) * C * 9;
    const float* inb = in + (size_t)b * PLANE;

    ull acc[COB][4];
#pragma unroll
    for (int i = 0; i < COB; i++)
#pragma unroll
        for (int j = 0; j < 4; j++) acc[i][j] = 0ULL;

    for (int ci = 0; ci < C; ci++) {
        __syncthreads();
        const float* ip = inb + (size_t)ci * IMG;
        for (int idx = tid; idx < 34 * 34; idx += 128) {
            int r = idx / 34, cc = idx % 34;
            int gy = y0 - 1 + r, gx = x0 - 1 + cc;
            float v = 0.f;
            if (gy >= 0 && gy < HW && gx >= 0 && gx < HW) v = ip[gy * HW + gx];
            tile[r * TSTRIDE + cc] = v;
        }
        for (int idx = tid; idx < COB * 9; idx += 128) {
            float wv = wbase[(idx / 9) * C * 9 + ci * 9 + (idx % 9)];
            wsm2[idx] = pk2(wv, wv);
        }
        __syncthreads();

        // pack input windows: win[s][dy][dx] = {tile[ty+8s+dy][2tx+dx],
        //                                       tile[ty+8s+16+dy][2tx+dx]}
        ull win[2][3][4];
#pragma unroll
        for (int s = 0; s < 2; s++) {
            int rbase = ty + 8 * s;
#pragma unroll
            for (int dy = 0; dy < 3; dy++)
#pragma unroll
                for (int dx = 0; dx < 4; dx++)
                    win[s][dy][dx] = pk2(
                        tile[(rbase + dy) * TSTRIDE + 2 * tx + dx],
                        tile[(rbase + 16 + dy) * TSTRIDE + 2 * tx + dx]);
        }

#pragma unroll
        for (int co = 0; co < COB; co++) {
            ull w0 = wsm2[co * 9 + 0], w1 = wsm2[co * 9 + 1], w2 = wsm2[co * 9 + 2];
            ull w3 = wsm2[co * 9 + 3], w4 = wsm2[co * 9 + 4], w5 = wsm2[co * 9 + 5];
            ull w6 = wsm2[co * 9 + 6], w7 = wsm2[co * 9 + 7], w8 = wsm2[co * 9 + 8];
#pragma unroll
            for (int s = 0; s < 2; s++)
#pragma unroll
                for (int xi = 0; xi < 2; xi++) {
                    ull a = acc[co][s * 2 + xi];
                    a = fma2(win[s][0][xi + 0], w0, a);
                    a = fma2(win[s][0][xi + 1], w1, a);
                    a = fma2(win[s][0][xi + 2], w2, a);
                    a = fma2(win[s][1][xi + 0], w3, a);
                    a = fma2(win[s][1][xi + 1], w4, a);
                    a = fma2(win[s][1][xi + 2], w5, a);
                    a = fma2(win[s][2][xi + 0], w6, a);
                    a = fma2(win[s][2][xi + 1], w7, a);
                    a = fma2(win[s][2][xi + 2], w8, a);
                    acc[co][s * 2 + xi] = a;
                }
        }
    }

    // stores (+ optional fused sum/sumsq stats)
    double ssum = 0.0, ssq = 0.0;
#pragma unroll
    for (int co = 0; co < COB; co++) {
        size_t ob = ((size_t)b * C + cog * COB + co) * IMG;
#pragma unroll
        for (int s = 0; s < 2; s++)
#pragma unroll
            for (int xi = 0; xi < 2; xi++) {
                float lo, hi;
                upk2(acc[co][s * 2 + xi], lo, hi);
                int row = y0 + ty + 8 * s;
                int col = x0 + 2 * tx + xi;
                out[ob + (size_t)row * HW + col] = lo;
                out[ob + (size_t)(row + 16) * HW + col] = hi;
                if (stats_base >= 0) {
                    ssum += (double)lo + (double)hi;
                    ssq  += (double)lo * lo + (double)hi * hi;
                }
            }
    }

    if (stats_base >= 0) {
        __syncthreads();
        double r = blk_reduce_d(ssum, sred, 128);
        if (tid == 0) atomicAdd(&g_stats[stats_base + 2 * b], r);
        r = blk_reduce_d(ssq, sred, 128);
        if (tid == 0) atomicAdd(&g_stats[stats_base + 2 * b + 1], r);
    }
}

// ---------------- stage 3: attention logits ----------------------------------
// attn[b,q,c,t] = sum over pixels (3ho+kh, 3wo+kw), ho,wo in [0,42)
__global__ void __launch_bounds__(256)
attn_logits_kernel() {
    int gz = blockIdx.x;
    int s = gz % ASPLIT; gz /= ASPLIT;
    int t = gz % 9;
    int b = gz / 9;
    int kh = t / 3, kw = t % 3;
    int tid = threadIdx.x;
    int qx = tid & 15;   // q tile index
    int cy = tid >> 4;   // c tile index

    __shared__ float Qs[42][97];
    __shared__ float Ks[42][97];

    float acc[6][6];
#pragma unroll
    for (int i = 0; i < 6; i++)
#pragma unroll
        for (int j = 0; j < 6; j++) acc[i][j] = 0.f;

    for (int ho = s * 7; ho < s * 7 + 7; ho++) {
        __syncthreads();
        int row = 3 * ho + kh;
        for (int idx = tid; idx < C * 42; idx += 256) {
            int ch = idx / 42, p = idx % 42;
            size_t a = ((size_t)b * C + ch) * IMG + (size_t)row * HW + (3 * p + kw);
            Qs[p][ch] = g_qry[a];
            Ks[p][ch] = g_key[a];
        }
        __syncthreads();
#pragma unroll 2
        for (int p = 0; p < 42; p++) {
            float qv[6], kv[6];
#pragma unroll
            for (int i = 0; i < 6; i++) {
                qv[i] = Qs[p][qx * 6 + i];
                kv[i] = Ks[p][cy * 6 + i];
            }
#pragma unroll
            for (int i = 0; i < 6; i++)
#pragma unroll
                for (int j = 0; j < 6; j++)
                    acc[i][j] = fmaf(kv[i], qv[j], acc[i][j]);
        }
    }
#pragma unroll
    for (int i = 0; i < 6; i++)
#pragma unroll
        for (int j = 0; j < 6; j++) {
            int q = qx * 6 + j, c = cy * 6 + i;
            g_attp[(((size_t)s * BATCH + b) * C + q) * CKK + c * 9 + t] = acc[i][j];
        }
}

// ---------------- stage 4: softmax over (c,t) --------------------------------
__global__ void __launch_bounds__(128)
softmax_kernel() {
    int b = blockIdx.x / C, q = blockIdx.x % C;
    int tid = threadIdx.x;
    __shared__ float red[128];
    const float scale = 0.034020690871988617f;   // 1/sqrt(864)

    float vals[7];
    float mx = -1e30f;
#pragma unroll
    for (int k = 0; k < 7; k++) {
        int j = tid + k * 128;
        if (j < CKK) {
            float v = 0.f;
#pragma unroll
            for (int s = 0; s < ASPLIT; s++)
                v += g_attp[(((size_t)s * BATCH + b) * C + q) * CKK + j];
            v *= scale;
            vals[k] = v;
            mx = fmaxf(mx, v);
        } else vals[k] = -1e30f;
    }
    red[tid] = mx; __syncthreads();
    for (int s = 64; s > 0; s >>= 1) {
        if (tid < s) red[tid] = fmaxf(red[tid], red[tid + s]);
        __syncthreads();
    }
    float M = red[0]; __syncthreads();

    float sum = 0.f;
#pragma unroll
    for (int k = 0; k < 7; k++) {
        int j = tid + k * 128;
        if (j < CKK) { vals[k] = expf(vals[k] - M); sum += vals[k]; }
    }
    red[tid] = sum; __syncthreads();
    for (int s = 64; s > 0; s >>= 1) {
        if (tid < s) red[tid] += red[tid + s];
        __syncthreads();
    }
    float inv = 1.f / red[0];
#pragma unroll
    for (int k = 0; k < 7; k++) {
        int j = tid + k * 128;
        if (j < CKK) g_attw[((size_t)b * C + q) * CKK + j] = vals[k] * inv;
    }
}

// ---------------- stage 5: finalize mean/var of g_att and g_c2 ----------------
__global__ void finalize2_kernel() {
    int b = threadIdx.x;
    if (b >= BATCH) return;
    const double N = (double)PLANE;
    double mA = g_stats[48 + 2 * b] / N;
    double vA = g_stats[48 + 2 * b + 1] / N - mA * mA;
    double mC = g_stats[64 + 2 * b] / N;
    double vC = g_stats[64 + 2 * b + 1] / N - mC * mC;
    float* cf = &g_coef[b * 16];
    cf[8]  = (float)mA;
    cf[9]  = (float)(1.0 / sqrt(vA + LN_EPS));
    cf[10] = (float)mC;
    cf[11] = (float)(1.0 / sqrt(vC + LN_EPS));
}

// ---------------- stage 6: fused layer_norms + gate + 1x1 conv + residual ----
// block: 32 pixels, all 96 outputs (4 chunks of 24), 192 threads.
#define FPX 32
#define FTHREADS 192
#define WPAD 28

__global__ void __launch_bounds__(FTHREADS)
final_kernel(const float* __restrict__ wf, const float* __restrict__ bias,
             float* __restrict__ outp) {
    __shared__ float wfT[192 * WPAD];   // [c][o_local], padded
    __shared__ float ys[192 * FPX];     // [c][px]

    int b  = blockIdx.y;
    int p0 = blockIdx.x * FPX;
    int tid = threadIdx.x;
    int oo = tid >> 5;        // 0..5  -> 4 outputs each within chunk
    int pp = tid & 31;        // 0..31 -> pixel

    const float* cf = &g_coef[b * 16];
    float mA = cf[8], invA = cf[9], mC = cf[10], invC = cf[11];

    // load y tile once: c in [0,192), 32 px
    for (int idx = tid; idx < 192 * FPX; idx += FTHREADS) {
        int c = idx >> 5, p = idx & 31;
        float v;
        if (c < 96) {
            v = (g_att[((size_t)b * C + c) * IMG + p0 + p] - mA) * invA;
        } else {
            int cc = c - 96;
            size_t a = ((size_t)b * C + cc) * IMG + p0 + p;
            v = (g_c2[a] - mC) * invC * g_x1[a];
        }
        ys[c * FPX + p] = v;
    }

    for (int og = 0; og < 4; og++) {
        __syncthreads();
        // load weight chunk: outputs [og*24, og*24+24), all 192 c
        for (int idx = tid; idx < 24 * 192; idx += FTHREADS) {
            int o = idx / 192, c = idx % 192;
            wfT[c * WPAD + o] = wf[(og * 24 + o) * 192 + c];
        }
        __syncthreads();

        float acc0 = 0.f, acc1 = 0.f, acc2 = 0.f, acc3 = 0.f;
#pragma unroll 4
        for (int c = 0; c < 192; c++) {
            float4 w4 = *(const float4*)(wfT + c * WPAD + oo * 4);
            float yv = ys[c * FPX + pp];
            acc0 = fmaf(w4.x, yv, acc0);
            acc1 = fmaf(w4.y, yv, acc1);
            acc2 = fmaf(w4.z, yv, acc2);
            acc3 = fmaf(w4.w, yv, acc3);
        }

        int obase = og * 24 + oo * 4;
        float accv[4] = {acc0, acc1, acc2, acc3};
#pragma unroll
        for (int i = 0; i < 4; i++) {
            int o = obase + i;
            size_t ob = ((size_t)b * C + o) * IMG + p0 + pp;
            outp[ob] = g_xr[ob] + __ldg(&bias[o]) + accv[i];
        }
    }
}

// ---------------- launcher ----------------------------------------------------
extern "C" void kernel_launch(void* const* d_in, const int* in_sizes, int n_in,
                              void* d_out, int out_size) {
    const float* x      = (const float*)d_in[0];
    const float* wconv2 = (const float*)d_in[1];
    const float* aw1    = (const float*)d_in[2];
    const float* aw2    = (const float*)d_in[3];
    const float* aw3    = (const float*)d_in[4];
    const float* wfull  = (const float*)d_in[5];
    const float* bfull  = (const float*)d_in[6];
    const float* sc1    = (const float*)d_in[7];
    const float* sc2    = (const float*)d_in[8];
    const float* resc   = (const float*)d_in[9];
    const float* nc1    = (const float*)d_in[10];
    const float* nc2    = (const float*)d_in[11];
    float* outp = (float*)d_out;

    zero_stats_kernel<<<1, 128>>>();
    reduce_sum_kernel<<<dim3(32, BATCH), 256>>>(x);
    reduce_pass2_kernel<<<dim3(32, BATCH), 256>>>(x);
    finalize1_kernel<<<1, 32>>>(sc1, sc2, resc, nc1, nc2);
    elementwise_kernel<<<dim3(PLANE / 1024, BATCH), 256>>>(x);

    dim3 cgrid(HW / TW, HW / TH, BATCH * (C / COB));
    conv3x3_kernel<<<cgrid, 128>>>(0, aw1,    -1, 3, 0, -1);  // key = conv(x1, aw1)
    conv3x3_kernel<<<cgrid, 128>>>(1, aw2,    -1, 4, 0, -1);  // qry = conv(x2, aw2)
    conv3x3_kernel<<<cgrid, 128>>>(0, aw3,    -1, 5, 0, -1);  // val = conv(x1, aw3)
    conv3x3_kernel<<<cgrid, 128>>>(1, wconv2, -1, 6, 0, 64);  // c2 + stats

    attn_logits_kernel<<<BATCH * 9 * ASPLIT, 256>>>();
    softmax_kernel<<<BATCH * C, 128>>>();

    conv3x3_kernel<<<cgrid, 128>>>(5, (const float*)0, 8, 7, 1, 48);  // att + stats

    finalize2_kernel<<<1, 32>>>();

    final_kernel<<<dim3(IMG / FPX, BATCH), FTHREADS>>>(wfull, bfull, outp);
}

// round 4
// speedup vs baseline: 1.4653x; 1.1897x over previous
#include <cuda_runtime.h>
#include <math.h>

#define BATCH 8
#define C 96
#define HW 128
#define IMG (HW*HW)          // 16384
#define PLANE (C*IMG)        // 1572864
#define TOT (BATCH*PLANE)    // 12582912
#define KK 9
#define CKK (C*KK)           // 864
#define ASPLIT 6             // split of the 42 patch-rows into 6 chunks of 7
#define LN_EPS 1e-5

typedef unsigned long long ull;

// ---------------- f32x2 packed math helpers ----------------------------------
__device__ __forceinline__ ull pk2(float a, float b) {
    ull r;
    asm("mov.b64 %0, {%1, %2};" : "=l"(r) : "f"(a), "f"(b));
    return r;
}
__device__ __forceinline__ void upk2(ull v, float& a, float& b) {
    asm("mov.b64 {%0, %1}, %2;" : "=f"(a), "=f"(b) : "l"(v));
}
__device__ __forceinline__ ull fma2(ull a, ull b, ull c) {
    ull d;
    asm("fma.rn.f32x2 %0, %1, %2, %3;" : "=l"(d) : "l"(a), "l"(b), "l"(c));
    return d;
}

// ---------------- scratch (device globals; no allocation allowed) -------------
__device__ float g_x1[TOT];     // x1_out = sc1*x1 + x1n
__device__ float g_x2[TOT];     // x2_out
__device__ float g_xr[TOT];     // residual branch output
__device__ float g_key[TOT];    // conv(x1_out, aw1)
__device__ float g_qry[TOT];    // conv(x2_out, aw2)
__device__ float g_val[TOT];    // conv(x1_out, aw3)
__device__ float g_c2[TOT];     // conv(x2_out, w_conv2)
__device__ float g_att[TOT];    // per-example attention conv output
__device__ float g_attp[ASPLIT*BATCH*C*CKK];  // partial logits
__device__ float g_attw[BATCH*C*CKK];         // softmax weights [b][q][c][3][3]
__device__ double g_stats[96];
__device__ float g_coef[BATCH*16];

// stats layout:
//  [b]               : sum(x)                      (pass 1)
//  [8 + 5b + 0..4]   : pos, s1, s1sq, s2, s2sq    (pass 2, on centered x)
//  [48 + 2b, +1]     : sum, sumsq of g_att        (fused into attn conv)
//  [64 + 2b, +1]     : sum, sumsq of g_c2         (fused into c2 conv)
// coef layout (per b, 16 floats):
//  0:m0 1:A1 2:B1 3:D1 4:A2 5:B2 6:D2 7:sc1 8:mA 9:invA 10:mC 11:invC
//  12:sc2 13:res_coef 14:nc1 15:nc2

__device__ __forceinline__ float* dev_buf(int s) {
    switch (s) {
        case 0: return g_x1;  case 1: return g_x2;  case 2: return g_xr;
        case 3: return g_key; case 4: return g_qry; case 5: return g_val;
        case 6: return g_c2;  case 7: return g_att; case 8: return g_attw;
    }
    return 0;
}

// ---------------- small helpers ----------------------------------------------
__device__ __forceinline__ double blk_reduce_d(double v, double* red, int nthr) {
    int tid = threadIdx.x;
    red[tid] = v; __syncthreads();
    for (int s = nthr >> 1; s > 0; s >>= 1) {
        if (tid < s) red[tid] += red[tid + s];
        __syncthreads();
    }
    double r = red[0]; __syncthreads();
    return r;
}

// ---------------- stage 0: stats ---------------------------------------------
__global__ void zero_stats_kernel() {
    if (threadIdx.x < 96) g_stats[threadIdx.x] = 0.0;
}

__global__ void reduce_sum_kernel(const float* __restrict__ x) {
    __shared__ double red[256];
    int b = blockIdx.y;
    const float* xp = x + (size_t)b * PLANE;
    double s = 0.0;
    for (int i = blockIdx.x * 256 + threadIdx.x; i < PLANE; i += 32 * 256)
        s += (double)xp[i];
    s = blk_reduce_d(s, red, 256);
    if (threadIdx.x == 0) atomicAdd(&g_stats[b], s);
}

__global__ void reduce_pass2_kernel(const float* __restrict__ x) {
    __shared__ double red[256];
    int b = blockIdx.y;
    float m0 = (float)(g_stats[b] * (1.0 / (double)PLANE));
    const float* xp = x + (size_t)b * PLANE;
    double pos = 0, s1 = 0, s1sq = 0, s2 = 0, s2sq = 0;
    for (int i = blockIdx.x * 256 + threadIdx.x; i < PLANE; i += 32 * 256) {
        float xc = xp[i] - m0;
        double d = (double)xc;
        if (xc > 0.f) { pos += 1.0; s1 += d; s1sq += d * d; }
        else          { s2 += d; s2sq += d * d; }
    }
    double r;
    r = blk_reduce_d(pos, red, 256);  if (threadIdx.x == 0) atomicAdd(&g_stats[8 + 5*b + 0], r);
    r = blk_reduce_d(s1,  red, 256);  if (threadIdx.x == 0) atomicAdd(&g_stats[8 + 5*b + 1], r);
    r = blk_reduce_d(s1sq,red, 256);  if (threadIdx.x == 0) atomicAdd(&g_stats[8 + 5*b + 2], r);
    r = blk_reduce_d(s2,  red, 256);  if (threadIdx.x == 0) atomicAdd(&g_stats[8 + 5*b + 3], r);
    r = blk_reduce_d(s2sq,red, 256);  if (threadIdx.x == 0) atomicAdd(&g_stats[8 + 5*b + 4], r);
}

__global__ void finalize1_kernel(const float* __restrict__ sc1p,
                                 const float* __restrict__ sc2p,
                                 const float* __restrict__ resp,
                                 const float* __restrict__ nc1p,
                                 const float* __restrict__ nc2p) {
    int b = threadIdx.x;
    if (b >= BATCH) return;
    const double N = (double)PLANE;
    double m0   = g_stats[b] / N;
    double pos  = g_stats[8 + 5*b + 0];
    double s1   = g_stats[8 + 5*b + 1];
    double s1sq = g_stats[8 + 5*b + 2];
    double s2   = g_stats[8 + 5*b + 3];
    double s2sq = g_stats[8 + 5*b + 4];
    double neg  = N - pos;
    double avg1 = s1 / pos;
    double avg2 = s2 / neg;
    double mu1  = (s1 + avg1 * neg) / N;
    double var1 = (s1sq + avg1 * avg1 * neg) / N - mu1 * mu1;
    double inv1 = 1.0 / sqrt(var1 + LN_EPS);
    double c1   = sqrt(pos / N);
    double A1   = c1 * inv1;
    double mu2  = (s2 + avg2 * pos) / N;
    double var2 = (s2sq + avg2 * avg2 * pos) / N - mu2 * mu2;
    double inv2 = 1.0 / sqrt(var2 + LN_EPS);
    double c2   = sqrt(neg / N);
    double A2   = c2 * inv2;
    float* cf = &g_coef[b * 16];
    cf[0] = (float)m0;
    cf[1] = (float)A1;
    cf[2] = (float)(-A1 * mu1);
    cf[3] = (float)(A1 * (avg1 - mu1));
    cf[4] = (float)A2;
    cf[5] = (float)(-A2 * mu2);
    cf[6] = (float)(A2 * (avg2 - mu2));
    cf[7]  = *sc1p;
    cf[12] = *sc2p;
    cf[13] = *resp;
    cf[14] = *nc1p;
    cf[15] = *nc2p;
}

// ---------------- stage 1: split-norm elementwise ----------------------------
__global__ void elementwise_kernel(const float* __restrict__ x) {
    int b = blockIdx.y;
    const float* cf = &g_coef[b * 16];
    float m0 = cf[0], A1 = cf[1], B1 = cf[2], D1 = cf[3];
    float A2 = cf[4], B2 = cf[5], D2 = cf[6];
    float sc1 = cf[7], sc2 = cf[12], res = cf[13], nc1 = cf[14], nc2 = cf[15];
    size_t base = (size_t)b * PLANE + (size_t)(blockIdx.x * 256 + threadIdx.x) * 4;
    float4 xv = *(const float4*)(x + base);
    float4 r1, r2, rr;
    float in[4] = {xv.x, xv.y, xv.z, xv.w};
    float o1[4], o2[4], orr[4];
#pragma unroll
    for (int k = 0; k < 4; k++) {
        float xc = in[k] - m0;
        float x1v, x1n, x2v, x2n;
        if (xc > 0.f) { x1v = xc; x1n = fmaf(A1, xc, B1); x2v = 0.f; x2n = D2; }
        else          { x1v = 0.f; x1n = D1; x2v = xc; x2n = fmaf(A2, xc, B2); }
        orr[k] = 0.5f * (nc1 * x1n + nc2 * x2n) + res * xc;
        o1[k]  = sc1 * x1v + x1n;
        o2[k]  = sc2 * x2v + x2n;
    }
    r1.x = o1[0]; r1.y = o1[1]; r1.z = o1[2]; r1.w = o1[3];
    r2.x = o2[0]; r2.y = o2[1]; r2.z = o2[2]; r2.w = o2[3];
    rr.x = orr[0]; rr.y = orr[1]; rr.z = orr[2]; rr.w = orr[3];
    *(float4*)(g_x1 + base) = r1;
    *(float4*)(g_x2 + base) = r2;
    *(float4*)(g_xr + base) = rr;
}

// ---------------- stage 2: 3x3 convolutions (packed f32x2, pipelined) ---------
// tile 32x32 px per block, 128 threads. Each thread: 8 output px packed into
// 4 f32x2 accumulators per output channel; COB=8 channels/block.
// Double-buffered smem tile + weights, hoisted addressing, 1 sync per ci.
#define TW 32
#define TH 32
#define COB 8
#define TSTRIDE 37
#define NSLOT 10           // ceil(34*34 / 128)

__global__ void __launch_bounds__(128)
conv3x3_kernel(int in_sel, const float* __restrict__ w_ext, int w_sel,
               int out_sel, int per_batch, int stats_base) {
    const float* in  = dev_buf(in_sel);
    const float* w   = (w_sel >= 0) ? dev_buf(w_sel) : w_ext;
    float* out       = dev_buf(out_sel);

    int bz  = blockIdx.z;
    int b   = bz / (C / COB);
    int cog = bz % (C / COB);
    int x0  = blockIdx.x * TW;
    int y0  = blockIdx.y * TH;
    int tid = threadIdx.x;
    int tx  = tid & 15;           // 0..15
    int ty  = tid >> 4;           // 0..7

    __shared__ float tile[2][34 * TSTRIDE];
    __shared__ ull   wsm2[2][COB * 9];
    __shared__ double sred[128];

    const float* wbase = w + (per_batch ? (size_t)b * C * C * 9 : 0)
                           + (size_t)(cog * COB) * C * 9;
    const float* inb = in + (size_t)b * PLANE;

    // ---- hoisted tile-slot addressing (fixed across ci) ----
    int   soff[NSLOT];    // smem slot offset
    int   goff[NSLOT];    // global offset within plane (valid slots)
    bool  okf[NSLOT];
#pragma unroll
    for (int k = 0; k < NSLOT; k++) {
        int idx = tid + k * 128;
        bool inrange = (idx < 34 * 34);
        int r = idx / 34, cc = idx - r * 34;
        int gy = y0 - 1 + r, gx = x0 - 1 + cc;
        bool ok = inrange && gy >= 0 && gy < HW && gx >= 0 && gx < HW;
        soff[k] = inrange ? (r * TSTRIDE + cc) : 0;
        goff[k] = ok ? (gy * HW + gx) : 0;
        okf[k]  = ok;
        if (inrange && !ok) {              // zero halo once in both buffers
            tile[0][soff[k]] = 0.f;
            tile[1][soff[k]] = 0.f;
        }
    }
    // weight fetch: thread tid<72 loads weight (tid/9, tid%9), step 9 per ci
    const float* wptr = 0;
    if (tid < 72) wptr = wbase + (tid / 9) * (C * 9) + (tid % 9);

    // ---- preload ci = 0 ----
#pragma unroll
    for (int k = 0; k < NSLOT; k++)
        if (okf[k]) tile[0][soff[k]] = __ldg(inb + goff[k]);
    if (tid < 72) { float wv = __ldg(wptr); wsm2[0][tid] = pk2(wv, wv); }

    ull acc[COB][4];
#pragma unroll
    for (int i = 0; i < COB; i++)
#pragma unroll
        for (int j = 0; j < 4; j++) acc[i][j] = 0ULL;

    __syncthreads();

    for (int ci = 0; ci < C; ci++) {
        int cb = ci & 1, nb = cb ^ 1;
        // issue next-plane loads first (overlap with compute below)
        if (ci + 1 < C) {
            const float* np = inb + (size_t)(ci + 1) * IMG;
#pragma unroll
            for (int k = 0; k < NSLOT; k++)
                if (okf[k]) tile[nb][soff[k]] = __ldg(np + goff[k]);
            if (tid < 72) {
                float wv = __ldg(wptr + (ci + 1) * 9);
                wsm2[nb][tid] = pk2(wv, wv);
            }
        }

        const float* tcur = tile[cb];
        // pack input windows: win[s][dy][dx] = {t[ty+8s+dy][2tx+dx],
        //                                       t[ty+8s+16+dy][2tx+dx]}
        ull win[2][3][4];
#pragma unroll
        for (int s = 0; s < 2; s++) {
            int rbase = ty + 8 * s;
#pragma unroll
            for (int dy = 0; dy < 3; dy++)
#pragma unroll
                for (int dx = 0; dx < 4; dx++)
                    win[s][dy][dx] = pk2(
                        tcur[(rbase + dy) * TSTRIDE + 2 * tx + dx],
                        tcur[(rbase + 16 + dy) * TSTRIDE + 2 * tx + dx]);
        }

        const ull* wc = wsm2[cb];
#pragma unroll
        for (int co = 0; co < COB; co++) {
            ull w0 = wc[co * 9 + 0], w1 = wc[co * 9 + 1], w2 = wc[co * 9 + 2];
            ull w3 = wc[co * 9 + 3], w4 = wc[co * 9 + 4], w5 = wc[co * 9 + 5];
            ull w6 = wc[co * 9 + 6], w7 = wc[co * 9 + 7], w8 = wc[co * 9 + 8];
#pragma unroll
            for (int s = 0; s < 2; s++)
#pragma unroll
                for (int xi = 0; xi < 2; xi++) {
                    ull a = acc[co][s * 2 + xi];
                    a = fma2(win[s][0][xi + 0], w0, a);
                    a = fma2(win[s][0][xi + 1], w1, a);
                    a = fma2(win[s][0][xi + 2], w2, a);
                    a = fma2(win[s][1][xi + 0], w3, a);
                    a = fma2(win[s][1][xi + 1], w4, a);
                    a = fma2(win[s][1][xi + 2], w5, a);
                    a = fma2(win[s][2][xi + 0], w6, a);
                    a = fma2(win[s][2][xi + 1], w7, a);
                    a = fma2(win[s][2][xi + 2], w8, a);
                    acc[co][s * 2 + xi] = a;
                }
        }
        __syncthreads();
    }

    // stores (+ optional fused sum/sumsq stats)
    double ssum = 0.0, ssq = 0.0;
#pragma unroll
    for (int co = 0; co < COB; co++) {
        size_t ob = ((size_t)b * C + cog * COB + co) * IMG;
#pragma unroll
        for (int s = 0; s < 2; s++)
#pragma unroll
            for (int xi = 0; xi < 2; xi++) {
                float lo, hi;
                upk2(acc[co][s * 2 + xi], lo, hi);
                int row = y0 + ty + 8 * s;
                int col = x0 + 2 * tx + xi;
                out[ob + (size_t)row * HW + col] = lo;
                out[ob + (size_t)(row + 16) * HW + col] = hi;
                if (stats_base >= 0) {
                    ssum += (double)lo + (double)hi;
                    ssq  += (double)lo * lo + (double)hi * hi;
                }
            }
    }

    if (stats_base >= 0) {
        __syncthreads();
        double r = blk_reduce_d(ssum, sred, 128);
        if (tid == 0) atomicAdd(&g_stats[stats_base + 2 * b], r);
        r = blk_reduce_d(ssq, sred, 128);
        if (tid == 0) atomicAdd(&g_stats[stats_base + 2 * b + 1], r);
    }
}

// ---------------- stage 3: attention logits ----------------------------------
// attn[b,q,c,t] = sum over pixels (3ho+kh, 3wo+kw), ho,wo in [0,42)
__global__ void __launch_bounds__(256)
attn_logits_kernel() {
    int gz = blockIdx.x;
    int s = gz % ASPLIT; gz /= ASPLIT;
    int t = gz % 9;
    int b = gz / 9;
    int kh = t / 3, kw = t % 3;
    int tid = threadIdx.x;
    int qx = tid & 15;   // q tile index
    int cy = tid >> 4;   // c tile index

    __shared__ float Qs[42][97];
    __shared__ float Ks[42][97];

    float acc[6][6];
#pragma unroll
    for (int i = 0; i < 6; i++)
#pragma unroll
        for (int j = 0; j < 6; j++) acc[i][j] = 0.f;

    for (int ho = s * 7; ho < s * 7 + 7; ho++) {
        __syncthreads();
        int row = 3 * ho + kh;
        for (int idx = tid; idx < C * 42; idx += 256) {
            int ch = idx / 42, p = idx % 42;
            size_t a = ((size_t)b * C + ch) * IMG + (size_t)row * HW + (3 * p + kw);
            Qs[p][ch] = g_qry[a];
            Ks[p][ch] = g_key[a];
        }
        __syncthreads();
#pragma unroll 2
        for (int p = 0; p < 42; p++) {
            float qv[6], kv[6];
#pragma unroll
            for (int i = 0; i < 6; i++) {
                qv[i] = Qs[p][qx * 6 + i];
                kv[i] = Ks[p][cy * 6 + i];
            }
#pragma unroll
            for (int i = 0; i < 6; i++)
#pragma unroll
                for (int j = 0; j < 6; j++)
                    acc[i][j] = fmaf(kv[i], qv[j], acc[i][j]);
        }
    }
#pragma unroll
    for (int i = 0; i < 6; i++)
#pragma unroll
        for (int j = 0; j < 6; j++) {
            int q = qx * 6 + j, c = cy * 6 + i;
            g_attp[(((size_t)s * BATCH + b) * C + q) * CKK + c * 9 + t] = acc[i][j];
        }
}

// ---------------- stage 4: softmax over (c,t) --------------------------------
__global__ void __launch_bounds__(128)
softmax_kernel() {
    int b = blockIdx.x / C, q = blockIdx.x % C;
    int tid = threadIdx.x;
    __shared__ float red[128];
    const float scale = 0.034020690871988617f;   // 1/sqrt(864)

    float vals[7];
    float mx = -1e30f;
#pragma unroll
    for (int k = 0; k < 7; k++) {
        int j = tid + k * 128;
        if (j < CKK) {
            float v = 0.f;
#pragma unroll
            for (int s = 0; s < ASPLIT; s++)
                v += g_attp[(((size_t)s * BATCH + b) * C + q) * CKK + j];
            v *= scale;
            vals[k] = v;
            mx = fmaxf(mx, v);
        } else vals[k] = -1e30f;
    }
    red[tid] = mx; __syncthreads();
    for (int s = 64; s > 0; s >>= 1) {
        if (tid < s) red[tid] = fmaxf(red[tid], red[tid + s]);
        __syncthreads();
    }
    float M = red[0]; __syncthreads();

    float sum = 0.f;
#pragma unroll
    for (int k = 0; k < 7; k++) {
        int j = tid + k * 128;
        if (j < CKK) { vals[k] = expf(vals[k] - M); sum += vals[k]; }
    }
    red[tid] = sum; __syncthreads();
    for (int s = 64; s > 0; s >>= 1) {
        if (tid < s) red[tid] += red[tid + s];
        __syncthreads();
    }
    float inv = 1.f / red[0];
#pragma unroll
    for (int k = 0; k < 7; k++) {
        int j = tid + k * 128;
        if (j < CKK) g_attw[((size_t)b * C + q) * CKK + j] = vals[k] * inv;
    }
}

// ---------------- stage 5: finalize mean/var of g_att and g_c2 ----------------
__global__ void finalize2_kernel() {
    int b = threadIdx.x;
    if (b >= BATCH) return;
    const double N = (double)PLANE;
    double mA = g_stats[48 + 2 * b] / N;
    double vA = g_stats[48 + 2 * b + 1] / N - mA * mA;
    double mC = g_stats[64 + 2 * b] / N;
    double vC = g_stats[64 + 2 * b + 1] / N - mC * mC;
    float* cf = &g_coef[b * 16];
    cf[8]  = (float)mA;
    cf[9]  = (float)(1.0 / sqrt(vA + LN_EPS));
    cf[10] = (float)mC;
    cf[11] = (float)(1.0 / sqrt(vC + LN_EPS));
}

// ---------------- stage 6: fused layer_norms + gate + 1x1 conv + residual ----
// block: 32 pixels, all 96 outputs (4 chunks of 24), 192 threads.
#define FPX 32
#define FTHREADS 192
#define WPAD 28

__global__ void __launch_bounds__(FTHREADS)
final_kernel(const float* __restrict__ wf, const float* __restrict__ bias,
             float* __restrict__ outp) {
    __shared__ float wfT[192 * WPAD];   // [c][o_local], padded
    __shared__ float ys[192 * FPX];     // [c][px]

    int b  = blockIdx.y;
    int p0 = blockIdx.x * FPX;
    int tid = threadIdx.x;
    int oo = tid >> 5;        // 0..5  -> 4 outputs each within chunk
    int pp = tid & 31;        // 0..31 -> pixel

    const float* cf = &g_coef[b * 16];
    float mA = cf[8], invA = cf[9], mC = cf[10], invC = cf[11];

    // load y tile once: c in [0,192), 32 px
    for (int idx = tid; idx < 192 * FPX; idx += FTHREADS) {
        int c = idx >> 5, p = idx & 31;
        float v;
        if (c < 96) {
            v = (g_att[((size_t)b * C + c) * IMG + p0 + p] - mA) * invA;
        } else {
            int cc = c - 96;
            size_t a = ((size_t)b * C + cc) * IMG + p0 + p;
            v = (g_c2[a] - mC) * invC * g_x1[a];
        }
        ys[c * FPX + p] = v;
    }

    for (int og = 0; og < 4; og++) {
        __syncthreads();
        // load weight chunk: outputs [og*24, og*24+24), all 192 c
        for (int idx = tid; idx < 24 * 192; idx += FTHREADS) {
            int o = idx / 192, c = idx % 192;
            wfT[c * WPAD + o] = wf[(og * 24 + o) * 192 + c];
        }
        __syncthreads();

        float acc0 = 0.f, acc1 = 0.f, acc2 = 0.f, acc3 = 0.f;
#pragma unroll 4
        for (int c = 0; c < 192; c++) {
            float4 w4 = *(const float4*)(wfT + c * WPAD + oo * 4);
            float yv = ys[c * FPX + pp];
            acc0 = fmaf(w4.x, yv, acc0);
            acc1 = fmaf(w4.y, yv, acc1);
            acc2 = fmaf(w4.z, yv, acc2);
            acc3 = fmaf(w4.w, yv, acc3);
        }

        int obase = og * 24 + oo * 4;
        float accv[4] = {acc0, acc1, acc2, acc3};
#pragma unroll
        for (int i = 0; i < 4; i++) {
            int o = obase + i;
            size_t ob = ((size_t)b * C + o) * IMG + p0 + pp;
            outp[ob] = g_xr[ob] + __ldg(&bias[o]) + accv[i];
        }
    }
}

// ---------------- launcher ----------------------------------------------------
extern "C" void kernel_launch(void* const* d_in, const int* in_sizes, int n_in,
                              void* d_out, int out_size) {
    const float* x      = (const float*)d_in[0];
    const float* wconv2 = (const float*)d_in[1];
    const float* aw1    = (const float*)d_in[2];
    const float* aw2    = (const float*)d_in[3];
    const float* aw3    = (const float*)d_in[4];
    const float* wfull  = (const float*)d_in[5];
    const float* bfull  = (const float*)d_in[6];
    const float* sc1    = (const float*)d_in[7];
    const float* sc2    = (const float*)d_in[8];
    const float* resc   = (const float*)d_in[9];
    const float* nc1    = (const float*)d_in[10];
    const float* nc2    = (const float*)d_in[11];
    float* outp = (float*)d_out;

    zero_stats_kernel<<<1, 128>>>();
    reduce_sum_kernel<<<dim3(32, BATCH), 256>>>(x);
    reduce_pass2_kernel<<<dim3(32, BATCH), 256>>>(x);
    finalize1_kernel<<<1, 32>>>(sc1, sc2, resc, nc1, nc2);
    elementwise_kernel<<<dim3(PLANE / 1024, BATCH), 256>>>(x);

    dim3 cgrid(HW / TW, HW / TH, BATCH * (C / COB));
    conv3x3_kernel<<<cgrid, 128>>>(0, aw1,    -1, 3, 0, -1);  // key = conv(x1, aw1)
    conv3x3_kernel<<<cgrid, 128>>>(1, aw2,    -1, 4, 0, -1);  // qry = conv(x2, aw2)
    conv3x3_kernel<<<cgrid, 128>>>(0, aw3,    -1, 5, 0, -1);  // val = conv(x1, aw3)
    conv3x3_kernel<<<cgrid, 128>>>(1, wconv2, -1, 6, 0, 64);  // c2 + stats

    attn_logits_kernel<<<BATCH * 9 * ASPLIT, 256>>>();
    softmax_kernel<<<BATCH * C, 128>>>();

    conv3x3_kernel<<<cgrid, 128>>>(5, (const float*)0, 8, 7, 1, 48);  // att + stats

    finalize2_kernel<<<1, 32>>>();

    final_kernel<<<dim3(IMG / FPX, BATCH), FTHREADS>>>(wfull, bfull, outp);
}